// round 15
// baseline (speedup 1.0000x reference)
#include <cuda_runtime.h>
#include <cuda_fp16.h>
#include <math.h>
#include <stdint.h>

#define BATCH 2
#define TSEQ  2048
#define EMB   1024
#define HEADS 16
#define DHEAD 64
#define DFF   4096
#define MROWS 4096   // BATCH*TSEQ

// -------- scratch --------
__device__ __half g_xn [(size_t)MROWS * EMB];
__device__ float  g_q  [(size_t)BATCH * HEADS * TSEQ * DHEAD];
__device__ float  g_k  [(size_t)BATCH * HEADS * TSEQ * DHEAD];
__device__ float  g_v  [(size_t)BATCH * HEADS * TSEQ * DHEAD];
__device__ __half g_att[(size_t)MROWS * EMB];
__device__ float  g_x1 [(size_t)MROWS * EMB];
__device__ __half g_h  [(size_t)MROWS * DFF];
// transposed (K-major, fp16) weights
__device__ __half g_wt  [(size_t)3 * EMB * EMB];   // [3072][1024] fused QKV
__device__ float  g_bqkv[3 * EMB];
__device__ __half g_wot [(size_t)EMB * EMB];       // [1024][1024]
__device__ __half g_w1t [(size_t)DFF * EMB];       // [4096][1024]
__device__ __half g_w2t [(size_t)EMB * DFF];       // [1024][4096]

// ---------------------------------------------------------------------------
// helpers
// ---------------------------------------------------------------------------
__device__ __forceinline__ unsigned f2tf32(float f) {
    unsigned u;
    asm("cvt.rna.tf32.f32 %0, %1;" : "=r"(u) : "f"(f));
    return u;
}
__device__ __forceinline__ void mma_tf32(float* d, const unsigned* a, const unsigned* b) {
    asm volatile(
        "mma.sync.aligned.m16n8k8.row.col.f32.tf32.tf32.f32 "
        "{%0,%1,%2,%3},{%4,%5,%6,%7},{%8,%9},{%0,%1,%2,%3};\n"
        : "+f"(d[0]), "+f"(d[1]), "+f"(d[2]), "+f"(d[3])
        : "r"(a[0]), "r"(a[1]), "r"(a[2]), "r"(a[3]), "r"(b[0]), "r"(b[1]));
}
__device__ __forceinline__ void mma_f16(float* d, const unsigned* a, const unsigned* b) {
    asm volatile(
        "mma.sync.aligned.m16n8k16.row.col.f32.f16.f16.f32 "
        "{%0,%1,%2,%3},{%4,%5,%6,%7},{%8,%9},{%0,%1,%2,%3};\n"
        : "+f"(d[0]), "+f"(d[1]), "+f"(d[2]), "+f"(d[3])
        : "r"(a[0]), "r"(a[1]), "r"(a[2]), "r"(a[3]), "r"(b[0]), "r"(b[1]));
}
__device__ __forceinline__ void ldsm4(unsigned* d, uint32_t a) {
    asm volatile("ldmatrix.sync.aligned.m8n8.x4.shared.b16 {%0,%1,%2,%3}, [%4];"
                 : "=r"(d[0]), "=r"(d[1]), "=r"(d[2]), "=r"(d[3]) : "r"(a));
}
__device__ __forceinline__ uint32_t s2u(const void* p) {
    uint32_t a;
    asm("{ .reg .u64 t; cvta.to.shared.u64 t, %1; cvt.u32.u64 %0, t; }"
        : "=r"(a) : "l"(p));
    return a;
}
__device__ __forceinline__ void cpa16(uint32_t dst, const void* src) {
    asm volatile("cp.async.cg.shared.global [%0], [%1], 16;"
                 :: "r"(dst), "l"(src) : "memory");
}
#define CP_COMMIT() asm volatile("cp.async.commit_group;" ::: "memory")
#define CP_WAIT1()  asm volatile("cp.async.wait_group 1;" ::: "memory")
#define CP_WAIT0()  asm volatile("cp.async.wait_group 0;" ::: "memory")

// ---------------------------------------------------------------------------
// LayerNorm — warp per row, 8 rows/block; fp16 output (GEMM A operand only)
// ---------------------------------------------------------------------------
__global__ __launch_bounds__(256) void ln_kernel(
    const float* __restrict__ in, const float* __restrict__ gamma,
    const float* __restrict__ beta, __half* __restrict__ out)
{
    const int row  = blockIdx.x * 8 + (threadIdx.x >> 5);
    const int lane = threadIdx.x & 31;
    const float* xr = in + (size_t)row * EMB;

    float4 xv[8];
    float s = 0.f;
    #pragma unroll
    for (int i = 0; i < 8; i++) {
        xv[i] = *(const float4*)(xr + (i * 32 + lane) * 4);
        s += xv[i].x + xv[i].y + xv[i].z + xv[i].w;
    }
    #pragma unroll
    for (int o = 16; o > 0; o >>= 1) s += __shfl_xor_sync(0xffffffffu, s, o);
    const float mu = s * (1.0f / EMB);

    float ss = 0.f;
    #pragma unroll
    for (int i = 0; i < 8; i++) {
        xv[i].x -= mu; xv[i].y -= mu; xv[i].z -= mu; xv[i].w -= mu;
        ss += xv[i].x * xv[i].x + xv[i].y * xv[i].y
            + xv[i].z * xv[i].z + xv[i].w * xv[i].w;
    }
    #pragma unroll
    for (int o = 16; o > 0; o >>= 1) ss += __shfl_xor_sync(0xffffffffu, ss, o);
    const float inv = rsqrtf(ss * (1.0f / EMB) + 1e-5f);

    __half* orow = out + (size_t)row * EMB;
    #pragma unroll
    for (int i = 0; i < 8; i++) {
        const int cc = (i * 32 + lane) * 4;
        float4 gv = *(const float4*)(gamma + cc);
        float4 bv = *(const float4*)(beta  + cc);
        half2 p0 = __floats2half2_rn(xv[i].x * inv * gv.x + bv.x,
                                     xv[i].y * inv * gv.y + bv.y);
        half2 p1 = __floats2half2_rn(xv[i].z * inv * gv.z + bv.z,
                                     xv[i].w * inv * gv.w + bv.w);
        *(half2*)(orow + cc)     = p0;
        *(half2*)(orow + cc + 2) = p1;
    }
}

// ---------------------------------------------------------------------------
// Weight transposes -> K-major [N,K], fp16
// ---------------------------------------------------------------------------
__global__ void trans_w(const float* __restrict__ in, __half* __restrict__ out,
                        int K, int N)
{   // in [K,N] -> out [N,K]; block (32,8), grid (N/32, K/32)
    __shared__ float t[32][33];
    const int n0 = blockIdx.x * 32, k0 = blockIdx.y * 32;
    const int tx = threadIdx.x, ty = threadIdx.y;
    #pragma unroll
    for (int i = 0; i < 32; i += 8)
        t[ty + i][tx] = in[(size_t)(k0 + ty + i) * N + n0 + tx];
    __syncthreads();
    #pragma unroll
    for (int i = 0; i < 32; i += 8)
        out[(size_t)(n0 + ty + i) * K + k0 + tx] = __float2half_rn(t[tx][ty + i]);
}

__global__ void trans_qkv(const float* __restrict__ Wq, const float* __restrict__ Wk,
                          const float* __restrict__ Wv, __half* __restrict__ out)
{   // W[z][h][E][64] -> out[(z*16+h)*64 + d][e]; grid (2, 32, 48), block (32,8)
    const int zh = blockIdx.z;
    const int z = zh >> 4;
    const float* W = (z == 0 ? Wq : z == 1 ? Wk : Wv) + (size_t)(zh & 15) * EMB * 64;
    __shared__ float t[32][33];
    const int d0 = blockIdx.x * 32, k0 = blockIdx.y * 32;
    const int tx = threadIdx.x, ty = threadIdx.y;
    #pragma unroll
    for (int i = 0; i < 32; i += 8)
        t[ty + i][tx] = W[(size_t)(k0 + ty + i) * 64 + d0 + tx];
    __syncthreads();
    __half* o = out + (size_t)zh * 64 * EMB;
    #pragma unroll
    for (int i = 0; i < 32; i += 8)
        o[(size_t)(d0 + ty + i) * EMB + k0 + tx] = __float2half_rn(t[tx][ty + i]);
}

__global__ void pack_bias(const float* __restrict__ bq, const float* __restrict__ bk,
                          const float* __restrict__ bv, float* __restrict__ o)
{
    const int n = blockIdx.x * 256 + threadIdx.x;
    const float* b = n < 1024 ? bq : n < 2048 ? bk : bv;
    o[n] = b[n & 1023];
}

// ---------------------------------------------------------------------------
// FP16 mma.sync GEMM (m16n8k16, fp32 acc): cp.async 3-stage + ldmatrix.
// CTA tile 128x128, k-chunk 64 halves (128B rows). A [M,K], Bt [N,K] fp16.
// 8 warps 2(M) x 4(N); warp tile 64x32.
// MODE 0: relu(acc+bias) -> fp16 C0; MODE 1: resid+acc+bias -> fp32 C0;
// MODE 2: QKV scatter, tf32-rounded fp32 (attention consumes as tf32)
// ---------------------------------------------------------------------------
#define STAGE_BYTES 32768      // A 16KB + B 16KB (128 rows x 128B each)
#define NSTAGE 3
#define SMEM_DYN (NSTAGE * STAGE_BYTES)

template<int MODE>
__global__ __launch_bounds__(256) void tc_gemm(
    const __half* __restrict__ A, const __half* __restrict__ Bt,
    const float* __restrict__ bias, const float* __restrict__ resid,
    float* __restrict__ C0, float* __restrict__ C1, float* __restrict__ C2,
    int N, int K)
{
    extern __shared__ char smem[];
    const uint32_t sb = s2u(smem);
    const int tid = threadIdx.x;
    const int lane = tid & 31, warp = tid >> 5;
    const int warpM = warp & 1, warpN = warp >> 1;
    const int lane7 = lane & 7;
    const int bm = blockIdx.y * 128, bn = blockIdx.x * 128;

    float acc[64];
    #pragma unroll
    for (int i = 0; i < 64; i++) acc[i] = 0.f;

    int rowA[4], chA[4];
    #pragma unroll
    for (int j = 0; j < 4; j++) {
        const int idx = j * 256 + tid;
        rowA[j] = idx >> 3;
        chA[j]  = idx & 7;
    }

    auto issue = [&](int t, int buf) {
        const int k0 = t << 6;                       // halves
        const uint32_t base = sb + buf * STAGE_BYTES;
        #pragma unroll
        for (int j = 0; j < 4; j++) {
            const int row = rowA[j], ch = chA[j];
            const uint32_t off = row * 128 + ((ch ^ (row & 7)) << 4);
            cpa16(base + off,          A  + (size_t)(bm + row) * K + k0 + ch * 8);
            cpa16(base + 16384 + off,  Bt + (size_t)(bn + row) * K + k0 + ch * 8);
        }
        CP_COMMIT();
    };

    // ldmatrix per-lane invariants (b16 native layout)
    const int mi = lane >> 3;                        // matrix index 0..3
    const int a_row = warpM * 64 + ((mi & 1) << 3) + lane7;
    const int a_chk = mi >> 1;                       // k-half select
    const int b_row = warpN * 32 + ((mi >> 1) << 3) + lane7;
    const int b_khf = mi & 1;

    const int nk = K >> 6;
    issue(0, 0);
    issue(1, 1);

    for (int t = 0; t < nk; ++t) {
        const int buf = t % NSTAGE;
        if (t + 2 < nk) { CP_WAIT1(); } else { CP_WAIT0(); }
        __syncthreads();
        if (t + 2 < nk) issue(t + 2, (t + 2) % NSTAGE);

        const uint32_t ab = sb + buf * STAGE_BYTES;
        const uint32_t bbp = ab + 16384;

        #pragma unroll
        for (int s = 0; s < 4; ++s) {               // four k16 steps per chunk
            unsigned af[4][4], bf[4][2];
            #pragma unroll
            for (int mt = 0; mt < 4; mt++) {
                const uint32_t addr = ab + (a_row + mt * 16) * 128 +
                    ((uint32_t)((2 * s + a_chk) ^ lane7) << 4);
                ldsm4(af[mt], addr);
            }
            #pragma unroll
            for (int jp = 0; jp < 2; jp++) {
                unsigned d[4];
                const uint32_t addr = bbp + (b_row + jp * 16) * 128 +
                    ((uint32_t)((2 * s + b_khf) ^ lane7) << 4);
                ldsm4(d, addr);
                bf[2 * jp][0]     = d[0]; bf[2 * jp][1]     = d[1];
                bf[2 * jp + 1][0] = d[2]; bf[2 * jp + 1][1] = d[3];
            }
            #pragma unroll
            for (int mt = 0; mt < 4; mt++)
                #pragma unroll
                for (int nt = 0; nt < 4; nt++)
                    mma_f16(&acc[(mt * 4 + nt) * 4], af[mt], bf[nt]);
        }
    }

    const int g = lane >> 2, c = lane & 3;
    #pragma unroll
    for (int mt = 0; mt < 4; mt++) {
        const int r0 = bm + warpM * 64 + mt * 16 + g;
        const int r1 = r0 + 8;
        #pragma unroll
        for (int nt = 0; nt < 4; nt++) {
            const int nn = bn + warpN * 32 + nt * 8 + 2 * c;
            const float* a = &acc[(mt * 4 + nt) * 4];
            float2 bb2 = *(const float2*)&bias[nn];
            float v00 = a[0] + bb2.x, v01 = a[1] + bb2.y;
            float v10 = a[2] + bb2.x, v11 = a[3] + bb2.y;
            if (MODE == 0) {
                __half* H = (__half*)C0;
                *(half2*)&H[(size_t)r0 * N + nn] =
                    __floats2half2_rn(fmaxf(v00, 0.f), fmaxf(v01, 0.f));
                *(half2*)&H[(size_t)r1 * N + nn] =
                    __floats2half2_rn(fmaxf(v10, 0.f), fmaxf(v11, 0.f));
            } else if (MODE == 1) {
                float2 rr0 = *(const float2*)&resid[(size_t)r0 * N + nn];
                float2 rr1 = *(const float2*)&resid[(size_t)r1 * N + nn];
                *(float2*)&C0[(size_t)r0 * N + nn] = make_float2(v00 + rr0.x, v01 + rr0.y);
                *(float2*)&C0[(size_t)r1 * N + nn] = make_float2(v10 + rr1.x, v11 + rr1.y);
            } else {
                // QKV scatter, tf32-rounded fp32 (attention mma operand)
                v00 = __uint_as_float(f2tf32(v00));
                v01 = __uint_as_float(f2tf32(v01));
                v10 = __uint_as_float(f2tf32(v10));
                v11 = __uint_as_float(f2tf32(v11));
                const int z = nn >> 10;
                float* O = (z == 0) ? C0 : (z == 1) ? C1 : C2;
                const int h = (nn & 1023) >> 6, d = nn & 63;
                const int b0 = r0 >> 11, t0i = r0 & 2047;
                const int b1 = r1 >> 11, t1i = r1 & 2047;
                *(float2*)&O[((((size_t)(b0 * HEADS + h)) * TSEQ + t0i) << 6) + d] =
                    make_float2(v00, v01);
                *(float2*)&O[((((size_t)(b1 * HEADS + h)) * TSEQ + t1i) << 6) + d] =
                    make_float2(v10, v11);
            }
        }
    }
}

// ---------------------------------------------------------------------------
// TF32 causal flash attention (unchanged math); output fp16 (feeds Wo GEMM)
// q-tile 128, 256 threads, kv tiles 64, cp.async loads.
// ---------------------------------------------------------------------------
#define ATTN_SMEM ((64 + 64 + 128) * 68 * 4)

__global__ __launch_bounds__(256) void attn_mma(
    const float* __restrict__ q, const float* __restrict__ k,
    const float* __restrict__ v, __half* __restrict__ out)
{
    extern __shared__ float sm[];
    float (*Ks)[68] = (float(*)[68])sm;
    float (*Vs)[68] = (float(*)[68])(sm + 64 * 68);
    float (*Ps)[68] = (float(*)[68])(sm + 128 * 68);

    const int bh = blockIdx.y;
    const int b = bh >> 4, h = bh & 15;
    const int qt = gridDim.x - 1 - blockIdx.x;   // heavy tiles first
    const int qbase = qt * 128;
    const float* Q  = q + (size_t)bh * TSEQ * DHEAD;
    const float* Kp = k + (size_t)bh * TSEQ * DHEAD;
    const float* Vp = v + (size_t)bh * TSEQ * DHEAD;

    const int tid = threadIdx.x;
    const int lane = tid & 31, w = tid >> 5;
    const int g = lane >> 2, c = lane & 3;
    const int r0 = w * 16 + g;

    unsigned qf[8][4];
    #pragma unroll
    for (int ks = 0; ks < 8; ks++) {
        const int kc = ks * 8;
        qf[ks][0] = __float_as_uint(0.125f * Q[(size_t)(qbase + r0)     * 64 + kc + c]);
        qf[ks][1] = __float_as_uint(0.125f * Q[(size_t)(qbase + r0 + 8) * 64 + kc + c]);
        qf[ks][2] = __float_as_uint(0.125f * Q[(size_t)(qbase + r0)     * 64 + kc + c + 4]);
        qf[ks][3] = __float_as_uint(0.125f * Q[(size_t)(qbase + r0 + 8) * 64 + kc + c + 4]);
    }

    float oacc[8][4];
    #pragma unroll
    for (int i = 0; i < 8; i++)
        #pragma unroll
        for (int j = 0; j < 4; j++) oacc[i][j] = 0.f;
    float m0 = -1e30f, m1 = -1e30f, l0 = 0.f, l1 = 0.f;

    const int ntiles = 2 * qt + 2;
    for (int t = 0; t < ntiles; t++) {
        const int kb = t * 64;
        __syncthreads();
        #pragma unroll
        for (int j = 0; j < 4; j++) {
            const int idx = j * 256 + tid;
            const int row = idx >> 4, col = (idx & 15) << 2;
            cpa16(s2u(&Ks[row][col]), &Kp[(size_t)(kb + row) * 64 + col]);
            cpa16(s2u(&Vs[row][col]), &Vp[(size_t)(kb + row) * 64 + col]);
        }
        CP_COMMIT();
        CP_WAIT0();
        __syncthreads();

        float sacc[8][4];
        #pragma unroll
        for (int i = 0; i < 8; i++)
            #pragma unroll
            for (int j = 0; j < 4; j++) sacc[i][j] = 0.f;
        #pragma unroll
        for (int ks = 0; ks < 8; ks++) {
            const int kc = ks * 8;
            #pragma unroll
            for (int nt = 0; nt < 8; nt++) {
                unsigned bf[2];
                bf[0] = __float_as_uint(Ks[nt * 8 + g][kc + c]);
                bf[1] = __float_as_uint(Ks[nt * 8 + g][kc + c + 4]);
                mma_tf32(sacc[nt], qf[ks], bf);
            }
        }

        if (t >= ntiles - 2) {
            const int rg0 = qbase + r0, rg1 = rg0 + 8;
            #pragma unroll
            for (int nt = 0; nt < 8; nt++) {
                const int c0 = kb + nt * 8 + 2 * c, c1 = c0 + 1;
                if (c0 > rg0) sacc[nt][0] = -1e30f;
                if (c1 > rg0) sacc[nt][1] = -1e30f;
                if (c0 > rg1) sacc[nt][2] = -1e30f;
                if (c1 > rg1) sacc[nt][3] = -1e30f;
            }
        }

        float mx0 = m0, mx1 = m1;
        #pragma unroll
        for (int nt = 0; nt < 8; nt++) {
            mx0 = fmaxf(mx0, fmaxf(sacc[nt][0], sacc[nt][1]));
            mx1 = fmaxf(mx1, fmaxf(sacc[nt][2], sacc[nt][3]));
        }
        #pragma unroll
        for (int o = 1; o <= 2; o <<= 1) {
            mx0 = fmaxf(mx0, __shfl_xor_sync(0xffffffffu, mx0, o));
            mx1 = fmaxf(mx1, __shfl_xor_sync(0xffffffffu, mx1, o));
        }
        const float rs0 = __expf(m0 - mx0), rs1 = __expf(m1 - mx1);
        m0 = mx0; m1 = mx1;

        float sum0 = 0.f, sum1 = 0.f;
        #pragma unroll
        for (int nt = 0; nt < 8; nt++) {
            const int cc = nt * 8 + 2 * c;
            float p00 = __expf(sacc[nt][0] - mx0);
            float p01 = __expf(sacc[nt][1] - mx0);
            float p10 = __expf(sacc[nt][2] - mx1);
            float p11 = __expf(sacc[nt][3] - mx1);
            sum0 += p00 + p01;
            sum1 += p10 + p11;
            *(float2*)&Ps[r0][cc] = make_float2(
                __uint_as_float(f2tf32(p00)), __uint_as_float(f2tf32(p01)));
            *(float2*)&Ps[r0 + 8][cc] = make_float2(
                __uint_as_float(f2tf32(p10)), __uint_as_float(f2tf32(p11)));
        }
        #pragma unroll
        for (int o = 1; o <= 2; o <<= 1) {
            sum0 += __shfl_xor_sync(0xffffffffu, sum0, o);
            sum1 += __shfl_xor_sync(0xffffffffu, sum1, o);
        }
        l0 = l0 * rs0 + sum0;
        l1 = l1 * rs1 + sum1;
        #pragma unroll
        for (int nt = 0; nt < 8; nt++) {
            oacc[nt][0] *= rs0; oacc[nt][1] *= rs0;
            oacc[nt][2] *= rs1; oacc[nt][3] *= rs1;
        }
        __syncwarp();

        #pragma unroll
        for (int ks = 0; ks < 8; ks++) {
            const int kc = ks * 8;
            unsigned af[4];
            af[0] = __float_as_uint(Ps[r0][kc + c]);
            af[1] = __float_as_uint(Ps[r0 + 8][kc + c]);
            af[2] = __float_as_uint(Ps[r0][kc + c + 4]);
            af[3] = __float_as_uint(Ps[r0 + 8][kc + c + 4]);
            #pragma unroll
            for (int nt = 0; nt < 8; nt++) {
                unsigned bf[2];
                bf[0] = __float_as_uint(Vs[kc + c][nt * 8 + g]);
                bf[1] = __float_as_uint(Vs[kc + c + 4][nt * 8 + g]);
                mma_tf32(oacc[nt], af, bf);
            }
        }
    }

    // normalize + write concat layout [B*T, E] as fp16 (Wo GEMM A operand)
    const float inv0 = 1.0f / l0, inv1 = 1.0f / l1;
    const size_t row0 = (size_t)(b * TSEQ + qbase + r0) * EMB + h * 64;
    const size_t row1 = row0 + (size_t)8 * EMB;
    #pragma unroll
    for (int nt = 0; nt < 8; nt++) {
        const int cc = nt * 8 + 2 * c;
        *(half2*)&out[row0 + cc] =
            __floats2half2_rn(oacc[nt][0] * inv0, oacc[nt][1] * inv0);
        *(half2*)&out[row1 + cc] =
            __floats2half2_rn(oacc[nt][2] * inv1, oacc[nt][3] * inv1);
    }
}

// ---------------------------------------------------------------------------
static void* sym_addr(const void* symbol)
{
    void* p = nullptr;
    cudaGetSymbolAddress(&p, symbol);
    return p;
}

extern "C" void kernel_launch(void* const* d_in, const int* in_sizes, int n_in,
                              void* d_out, int out_size)
{
    (void)in_sizes; (void)n_in; (void)out_size;
    const float* x      = (const float*)d_in[0];
    const float* Wq     = (const float*)d_in[1];
    const float* bq     = (const float*)d_in[2];
    const float* Wk     = (const float*)d_in[3];
    const float* bk     = (const float*)d_in[4];
    const float* Wv     = (const float*)d_in[5];
    const float* bv     = (const float*)d_in[6];
    const float* Wo     = (const float*)d_in[7];
    const float* bo     = (const float*)d_in[8];
    const float* W1     = (const float*)d_in[9];
    const float* b1     = (const float*)d_in[10];
    const float* W2     = (const float*)d_in[11];
    const float* b2     = (const float*)d_in[12];
    const float* gamma1 = (const float*)d_in[13];
    const float* beta1  = (const float*)d_in[14];
    const float* gamma2 = (const float*)d_in[15];
    const float* beta2  = (const float*)d_in[16];
    float* out = (float*)d_out;

    __half* xn   = (__half*)sym_addr(g_xn);
    float*  qb   = (float*) sym_addr(g_q);
    float*  kb2  = (float*) sym_addr(g_k);
    float*  vb2  = (float*) sym_addr(g_v);
    __half* att  = (__half*)sym_addr(g_att);
    float*  x1   = (float*) sym_addr(g_x1);
    __half* hb   = (__half*)sym_addr(g_h);
    __half* wt   = (__half*)sym_addr(g_wt);
    float*  bqkv = (float*) sym_addr(g_bqkv);
    __half* wot  = (__half*)sym_addr(g_wot);
    __half* w1t  = (__half*)sym_addr(g_w1t);
    __half* w2t  = (__half*)sym_addr(g_w2t);

    cudaFuncSetAttribute(tc_gemm<0>, cudaFuncAttributeMaxDynamicSharedMemorySize, SMEM_DYN);
    cudaFuncSetAttribute(tc_gemm<1>, cudaFuncAttributeMaxDynamicSharedMemorySize, SMEM_DYN);
    cudaFuncSetAttribute(tc_gemm<2>, cudaFuncAttributeMaxDynamicSharedMemorySize, SMEM_DYN);
    cudaFuncSetAttribute(attn_mma,  cudaFuncAttributeMaxDynamicSharedMemorySize, ATTN_SMEM);

    // 0. weight transposes (fp16) and bias pack
    trans_qkv<<<dim3(2, 32, 48), dim3(32, 8)>>>(Wq, Wk, Wv, wt);
    pack_bias<<<12, 256>>>(bq, bk, bv, bqkv);
    trans_w<<<dim3(32, 32),  dim3(32, 8)>>>(Wo, wot, EMB, EMB);
    trans_w<<<dim3(128, 32), dim3(32, 8)>>>(W1, w1t, EMB, DFF);
    trans_w<<<dim3(32, 128), dim3(32, 8)>>>(W2, w2t, DFF, EMB);

    // 1. LN1 -> fp16
    ln_kernel<<<MROWS / 8, 256>>>(x, gamma1, beta1, xn);
    // 2. fused QKV projection (fp16 mma) -> fp32 tf32-rounded q/k/v
    tc_gemm<2><<<dim3(24, 32), 256, SMEM_DYN>>>(
        xn, wt, bqkv, nullptr, qb, kb2, vb2, 3 * EMB, EMB);
    // 3. causal attention -> fp16 [B*T, E]
    attn_mma<<<dim3(TSEQ / 128, BATCH * HEADS), 256, ATTN_SMEM>>>(qb, kb2, vb2, att);
    // 4. output projection + residual -> fp32 x1
    tc_gemm<1><<<dim3(8, 32), 256, SMEM_DYN>>>(
        att, wot, bo, x, x1, nullptr, nullptr, EMB, EMB);
    // 5. LN2 -> fp16
    ln_kernel<<<MROWS / 8, 256>>>(x1, gamma2, beta2, xn);
    // 6. FFN1 (relu) -> fp16 h
    tc_gemm<0><<<dim3(32, 32), 256, SMEM_DYN>>>(
        xn, w1t, b1, nullptr, (float*)hb, nullptr, nullptr, DFF, EMB);
    // 7. FFN2 + residual -> fp32 out
    tc_gemm<1><<<dim3(8, 32), 256, SMEM_DYN>>>(
        hb, w2t, b2, x1, out, nullptr, nullptr, EMB, DFF);
}

// round 17
// speedup vs baseline: 1.0691x; 1.0691x over previous
#include <cuda_runtime.h>
#include <math.h>
#include <stdint.h>

#define BATCH 2
#define TSEQ  2048
#define EMB   1024
#define HEADS 16
#define DHEAD 64
#define DFF   4096
#define MROWS 4096   // BATCH*TSEQ

// -------- scratch --------
__device__ float g_xn [(size_t)MROWS * EMB];
__device__ float g_q  [(size_t)BATCH * HEADS * TSEQ * DHEAD];
__device__ float g_k  [(size_t)BATCH * HEADS * TSEQ * DHEAD];
__device__ float g_v  [(size_t)BATCH * HEADS * TSEQ * DHEAD];
__device__ float g_att[(size_t)MROWS * EMB];
__device__ float g_x1 [(size_t)MROWS * EMB];
__device__ float g_h  [(size_t)MROWS * DFF];
// transposed (K-major, tf32-rounded) weights
__device__ float g_wt  [(size_t)3 * EMB * EMB];   // [3072][1024] fused QKV
__device__ float g_bqkv[3 * EMB];
__device__ float g_wot [(size_t)EMB * EMB];       // [1024][1024]
__device__ float g_w1t [(size_t)DFF * EMB];       // [4096][1024]
__device__ float g_w2t [(size_t)EMB * DFF];       // [1024][4096]

// ---------------------------------------------------------------------------
// helpers
// ---------------------------------------------------------------------------
__device__ __forceinline__ unsigned f2tf32(float f) {
    unsigned u;
    asm("cvt.rna.tf32.f32 %0, %1;" : "=r"(u) : "f"(f));
    return u;
}
__device__ __forceinline__ void mma_tf32(float* d, const unsigned* a, const unsigned* b) {
    asm volatile(
        "mma.sync.aligned.m16n8k8.row.col.f32.tf32.tf32.f32 "
        "{%0,%1,%2,%3},{%4,%5,%6,%7},{%8,%9},{%0,%1,%2,%3};\n"
        : "+f"(d[0]), "+f"(d[1]), "+f"(d[2]), "+f"(d[3])
        : "r"(a[0]), "r"(a[1]), "r"(a[2]), "r"(a[3]), "r"(b[0]), "r"(b[1]));
}
__device__ __forceinline__ void ldsm4(unsigned* d, uint32_t a) {
    asm volatile("ldmatrix.sync.aligned.m8n8.x4.shared.b16 {%0,%1,%2,%3}, [%4];"
                 : "=r"(d[0]), "=r"(d[1]), "=r"(d[2]), "=r"(d[3]) : "r"(a));
}
__device__ __forceinline__ uint32_t s2u(const void* p) {
    uint32_t a;
    asm("{ .reg .u64 t; cvta.to.shared.u64 t, %1; cvt.u32.u64 %0, t; }"
        : "=r"(a) : "l"(p));
    return a;
}
__device__ __forceinline__ void cpa16(uint32_t dst, const void* src) {
    asm volatile("cp.async.cg.shared.global [%0], [%1], 16;"
                 :: "r"(dst), "l"(src) : "memory");
}
#define CP_COMMIT() asm volatile("cp.async.commit_group;" ::: "memory")
#define CP_WAIT1()  asm volatile("cp.async.wait_group 1;" ::: "memory")
#define CP_WAIT0()  asm volatile("cp.async.wait_group 0;" ::: "memory")

// ---------------------------------------------------------------------------
// LayerNorm — warp per row, 8 rows/block; tf32-rounded output
// ---------------------------------------------------------------------------
__global__ __launch_bounds__(256) void ln_kernel(
    const float* __restrict__ in, const float* __restrict__ gamma,
    const float* __restrict__ beta, float* __restrict__ out)
{
    const int row  = blockIdx.x * 8 + (threadIdx.x >> 5);
    const int lane = threadIdx.x & 31;
    const float* xr = in + (size_t)row * EMB;

    float4 xv[8];
    float s = 0.f;
    #pragma unroll
    for (int i = 0; i < 8; i++) {
        xv[i] = *(const float4*)(xr + (i * 32 + lane) * 4);
        s += xv[i].x + xv[i].y + xv[i].z + xv[i].w;
    }
    #pragma unroll
    for (int o = 16; o > 0; o >>= 1) s += __shfl_xor_sync(0xffffffffu, s, o);
    const float mu = s * (1.0f / EMB);

    float ss = 0.f;
    #pragma unroll
    for (int i = 0; i < 8; i++) {
        xv[i].x -= mu; xv[i].y -= mu; xv[i].z -= mu; xv[i].w -= mu;
        ss += xv[i].x * xv[i].x + xv[i].y * xv[i].y
            + xv[i].z * xv[i].z + xv[i].w * xv[i].w;
    }
    #pragma unroll
    for (int o = 16; o > 0; o >>= 1) ss += __shfl_xor_sync(0xffffffffu, ss, o);
    const float inv = rsqrtf(ss * (1.0f / EMB) + 1e-5f);

    float* orow = out + (size_t)row * EMB;
    #pragma unroll
    for (int i = 0; i < 8; i++) {
        const int cc = (i * 32 + lane) * 4;
        float4 gv = *(const float4*)(gamma + cc);
        float4 bv = *(const float4*)(beta  + cc);
        float4 r;
        r.x = __uint_as_float(f2tf32(xv[i].x * inv * gv.x + bv.x));
        r.y = __uint_as_float(f2tf32(xv[i].y * inv * gv.y + bv.y));
        r.z = __uint_as_float(f2tf32(xv[i].z * inv * gv.z + bv.z));
        r.w = __uint_as_float(f2tf32(xv[i].w * inv * gv.w + bv.w));
        *(float4*)(orow + cc) = r;
    }
}

// ---------------------------------------------------------------------------
// Weight transposes -> K-major [N,K], tf32-pre-rounded
// ---------------------------------------------------------------------------
__global__ void trans_w(const float* __restrict__ in, float* __restrict__ out,
                        int K, int N)
{   // in [K,N] -> out [N,K]; block (32,8), grid (N/32, K/32)
    __shared__ float t[32][33];
    const int n0 = blockIdx.x * 32, k0 = blockIdx.y * 32;
    const int tx = threadIdx.x, ty = threadIdx.y;
    #pragma unroll
    for (int i = 0; i < 32; i += 8)
        t[ty + i][tx] = in[(size_t)(k0 + ty + i) * N + n0 + tx];
    __syncthreads();
    #pragma unroll
    for (int i = 0; i < 32; i += 8)
        out[(size_t)(n0 + ty + i) * K + k0 + tx] =
            __uint_as_float(f2tf32(t[tx][ty + i]));
}

__global__ void trans_qkv(const float* __restrict__ Wq, const float* __restrict__ Wk,
                          const float* __restrict__ Wv, float* __restrict__ out)
{   // W[z][h][E][64] -> out[(z*16+h)*64 + d][e]; grid (2, 32, 48), block (32,8)
    const int zh = blockIdx.z;
    const int z = zh >> 4;
    const float* W = (z == 0 ? Wq : z == 1 ? Wk : Wv) + (size_t)(zh & 15) * EMB * 64;
    __shared__ float t[32][33];
    const int d0 = blockIdx.x * 32, k0 = blockIdx.y * 32;
    const int tx = threadIdx.x, ty = threadIdx.y;
    #pragma unroll
    for (int i = 0; i < 32; i += 8)
        t[ty + i][tx] = W[(size_t)(k0 + ty + i) * 64 + d0 + tx];
    __syncthreads();
    float* o = out + (size_t)zh * 64 * EMB;
    #pragma unroll
    for (int i = 0; i < 32; i += 8)
        o[(size_t)(d0 + ty + i) * EMB + k0 + tx] =
            __uint_as_float(f2tf32(t[tx][ty + i]));
}

__global__ void pack_bias(const float* __restrict__ bq, const float* __restrict__ bk,
                          const float* __restrict__ bv, float* __restrict__ o)
{
    const int n = blockIdx.x * 256 + threadIdx.x;
    const float* b = n < 1024 ? bq : n < 2048 ? bk : bv;
    o[n] = b[n & 1023];
}

// ---------------------------------------------------------------------------
// TF32 mma.sync GEMM: cp.async 3-stage pipeline + ldmatrix (R13 baseline)
// MODE 0: relu(acc+bias) tf32; MODE 1: resid+acc+bias; MODE 2: QKV scatter tf32
// ---------------------------------------------------------------------------
#define STAGE_BYTES 32768
#define NSTAGE 3
#define SMEM_DYN (NSTAGE * STAGE_BYTES)

template<int MODE>
__global__ __launch_bounds__(256) void tc_gemm(
    const float* __restrict__ A, const float* __restrict__ Bt,
    const float* __restrict__ bias, const float* __restrict__ resid,
    float* __restrict__ C0, float* __restrict__ C1, float* __restrict__ C2,
    int N, int K)
{
    extern __shared__ char smem[];
    const uint32_t sb = s2u(smem);
    const int tid = threadIdx.x;
    const int lane = tid & 31, warp = tid >> 5;
    const int warpM = warp & 1, warpN = warp >> 1;
    const int lane7 = lane & 7;
    const int bm = blockIdx.y * 128, bn = blockIdx.x * 128;

    float acc[64];
    #pragma unroll
    for (int i = 0; i < 64; i++) acc[i] = 0.f;

    int rowA[4], chA[4];
    #pragma unroll
    for (int j = 0; j < 4; j++) {
        const int idx = j * 256 + tid;
        rowA[j] = idx >> 3;
        chA[j]  = idx & 7;
    }

    auto issue = [&](int t, int buf) {
        const int k0 = t << 5;
        const uint32_t base = sb + buf * STAGE_BYTES;
        #pragma unroll
        for (int j = 0; j < 4; j++) {
            const int row = rowA[j], ch = chA[j];
            const uint32_t off = row * 128 + ((ch ^ (row & 7)) << 4);
            cpa16(base + off,          A  + (size_t)(bm + row) * K + k0 + ch * 4);
            cpa16(base + 16384 + off,  Bt + (size_t)(bn + row) * K + k0 + ch * 4);
        }
        CP_COMMIT();
    };

    const int a_row_base = warpM * 64 + lane7 + ((lane >> 3) & 1) * 8;
    const int a_ch_sel   = lane >> 4;
    const int b_msel     = lane >> 3;
    const int b_row_base = warpN * 32 + (b_msel >> 1) * 8 + lane7;
    const int b_ch_sel   = b_msel & 1;

    const int nk = K >> 5;
    issue(0, 0);
    issue(1, 1);

    for (int t = 0; t < nk; ++t) {
        const int buf = t % NSTAGE;
        if (t + 2 < nk) { CP_WAIT1(); } else { CP_WAIT0(); }
        __syncthreads();
        if (t + 2 < nk) issue(t + 2, (t + 2) % NSTAGE);

        const uint32_t ab = sb + buf * STAGE_BYTES;
        const uint32_t bb = ab + 16384;
        const uint32_t aBase = ab + a_row_base * 128;

        #pragma unroll
        for (int ks = 0; ks < 4; ++ks) {
            unsigned af[4][4], bf[4][2];
            #pragma unroll
            for (int mt = 0; mt < 4; mt++) {
                const uint32_t addr = aBase + mt * 2048 +
                    ((uint32_t)((2 * ks + a_ch_sel) ^ lane7) << 4);
                ldsm4(af[mt], addr);
            }
            #pragma unroll
            for (int j = 0; j < 2; j++) {
                unsigned d[4];
                const uint32_t addr = bb + (b_row_base + j * 16) * 128 +
                    ((uint32_t)((2 * ks + b_ch_sel) ^ lane7) << 4);
                ldsm4(d, addr);
                bf[2 * j][0]     = d[0]; bf[2 * j][1]     = d[1];
                bf[2 * j + 1][0] = d[2]; bf[2 * j + 1][1] = d[3];
            }
            #pragma unroll
            for (int mt = 0; mt < 4; mt++)
                #pragma unroll
                for (int nt = 0; nt < 4; nt++)
                    mma_tf32(&acc[(mt * 4 + nt) * 4], af[mt], bf[nt]);
        }
    }

    const int g = lane >> 2, c = lane & 3;
    #pragma unroll
    for (int mt = 0; mt < 4; mt++) {
        const int r0 = bm + warpM * 64 + mt * 16 + g;
        const int r1 = r0 + 8;
        #pragma unroll
        for (int nt = 0; nt < 4; nt++) {
            const int nn = bn + warpN * 32 + nt * 8 + 2 * c;
            const float* a = &acc[(mt * 4 + nt) * 4];
            float2 bb2 = *(const float2*)&bias[nn];
            float v00 = a[0] + bb2.x, v01 = a[1] + bb2.y;
            float v10 = a[2] + bb2.x, v11 = a[3] + bb2.y;
            if (MODE == 0) {
                v00 = __uint_as_float(f2tf32(fmaxf(v00, 0.f)));
                v01 = __uint_as_float(f2tf32(fmaxf(v01, 0.f)));
                v10 = __uint_as_float(f2tf32(fmaxf(v10, 0.f)));
                v11 = __uint_as_float(f2tf32(fmaxf(v11, 0.f)));
                *(float2*)&C0[(size_t)r0 * N + nn] = make_float2(v00, v01);
                *(float2*)&C0[(size_t)r1 * N + nn] = make_float2(v10, v11);
            } else if (MODE == 1) {
                float2 rr0 = *(const float2*)&resid[(size_t)r0 * N + nn];
                float2 rr1 = *(const float2*)&resid[(size_t)r1 * N + nn];
                *(float2*)&C0[(size_t)r0 * N + nn] = make_float2(v00 + rr0.x, v01 + rr0.y);
                *(float2*)&C0[(size_t)r1 * N + nn] = make_float2(v10 + rr1.x, v11 + rr1.y);
            } else {
                v00 = __uint_as_float(f2tf32(v00));
                v01 = __uint_as_float(f2tf32(v01));
                v10 = __uint_as_float(f2tf32(v10));
                v11 = __uint_as_float(f2tf32(v11));
                const int z = nn >> 10;
                float* O = (z == 0) ? C0 : (z == 1) ? C1 : C2;
                const int h = (nn & 1023) >> 6, d = nn & 63;
                const int b0 = r0 >> 11, t0i = r0 & 2047;
                const int b1 = r1 >> 11, t1i = r1 & 2047;
                *(float2*)&O[((((size_t)(b0 * HEADS + h)) * TSEQ + t0i) << 6) + d] =
                    make_float2(v00, v01);
                *(float2*)&O[((((size_t)(b1 * HEADS + h)) * TSEQ + t1i) << 6) + d] =
                    make_float2(v10, v11);
            }
        }
    }
}

// ---------------------------------------------------------------------------
// TF32 causal flash attention: q-tile 128, 256 threads, kv tiles 64 (R13)
// ---------------------------------------------------------------------------
#define ATTN_SMEM ((64 + 64 + 128) * 68 * 4)

__global__ __launch_bounds__(256) void attn_mma(
    const float* __restrict__ q, const float* __restrict__ k,
    const float* __restrict__ v, float* __restrict__ out)
{
    extern __shared__ float sm[];
    float (*Ks)[68] = (float(*)[68])sm;
    float (*Vs)[68] = (float(*)[68])(sm + 64 * 68);
    float (*Ps)[68] = (float(*)[68])(sm + 128 * 68);

    const int bh = blockIdx.y;
    const int b = bh >> 4, h = bh & 15;
    const int qt = gridDim.x - 1 - blockIdx.x;   // heavy tiles first
    const int qbase = qt * 128;
    const float* Q  = q + (size_t)bh * TSEQ * DHEAD;
    const float* Kp = k + (size_t)bh * TSEQ * DHEAD;
    const float* Vp = v + (size_t)bh * TSEQ * DHEAD;

    const int tid = threadIdx.x;
    const int lane = tid & 31, w = tid >> 5;
    const int g = lane >> 2, c = lane & 3;
    const int r0 = w * 16 + g;

    unsigned qf[8][4];
    #pragma unroll
    for (int ks = 0; ks < 8; ks++) {
        const int kc = ks * 8;
        qf[ks][0] = __float_as_uint(0.125f * Q[(size_t)(qbase + r0)     * 64 + kc + c]);
        qf[ks][1] = __float_as_uint(0.125f * Q[(size_t)(qbase + r0 + 8) * 64 + kc + c]);
        qf[ks][2] = __float_as_uint(0.125f * Q[(size_t)(qbase + r0)     * 64 + kc + c + 4]);
        qf[ks][3] = __float_as_uint(0.125f * Q[(size_t)(qbase + r0 + 8) * 64 + kc + c + 4]);
    }

    float oacc[8][4];
    #pragma unroll
    for (int i = 0; i < 8; i++)
        #pragma unroll
        for (int j = 0; j < 4; j++) oacc[i][j] = 0.f;
    float m0 = -1e30f, m1 = -1e30f, l0 = 0.f, l1 = 0.f;

    const int ntiles = 2 * qt + 2;
    for (int t = 0; t < ntiles; t++) {
        const int kb = t * 64;
        __syncthreads();
        #pragma unroll
        for (int j = 0; j < 4; j++) {
            const int idx = j * 256 + tid;
            const int row = idx >> 4, col = (idx & 15) << 2;
            cpa16(s2u(&Ks[row][col]), &Kp[(size_t)(kb + row) * 64 + col]);
            cpa16(s2u(&Vs[row][col]), &Vp[(size_t)(kb + row) * 64 + col]);
        }
        CP_COMMIT();
        CP_WAIT0();
        __syncthreads();

        float sacc[8][4];
        #pragma unroll
        for (int i = 0; i < 8; i++)
            #pragma unroll
            for (int j = 0; j < 4; j++) sacc[i][j] = 0.f;
        #pragma unroll
        for (int ks = 0; ks < 8; ks++) {
            const int kc = ks * 8;
            #pragma unroll
            for (int nt = 0; nt < 8; nt++) {
                unsigned bf[2];
                bf[0] = __float_as_uint(Ks[nt * 8 + g][kc + c]);
                bf[1] = __float_as_uint(Ks[nt * 8 + g][kc + c + 4]);
                mma_tf32(sacc[nt], qf[ks], bf);
            }
        }

        if (t >= ntiles - 2) {
            const int rg0 = qbase + r0, rg1 = rg0 + 8;
            #pragma unroll
            for (int nt = 0; nt < 8; nt++) {
                const int c0 = kb + nt * 8 + 2 * c, c1 = c0 + 1;
                if (c0 > rg0) sacc[nt][0] = -1e30f;
                if (c1 > rg0) sacc[nt][1] = -1e30f;
                if (c0 > rg1) sacc[nt][2] = -1e30f;
                if (c1 > rg1) sacc[nt][3] = -1e30f;
            }
        }

        float mx0 = m0, mx1 = m1;
        #pragma unroll
        for (int nt = 0; nt < 8; nt++) {
            mx0 = fmaxf(mx0, fmaxf(sacc[nt][0], sacc[nt][1]));
            mx1 = fmaxf(mx1, fmaxf(sacc[nt][2], sacc[nt][3]));
        }
        #pragma unroll
        for (int o = 1; o <= 2; o <<= 1) {
            mx0 = fmaxf(mx0, __shfl_xor_sync(0xffffffffu, mx0, o));
            mx1 = fmaxf(mx1, __shfl_xor_sync(0xffffffffu, mx1, o));
        }
        const float rs0 = __expf(m0 - mx0), rs1 = __expf(m1 - mx1);
        m0 = mx0; m1 = mx1;

        float sum0 = 0.f, sum1 = 0.f;
        #pragma unroll
        for (int nt = 0; nt < 8; nt++) {
            const int cc = nt * 8 + 2 * c;
            float p00 = __expf(sacc[nt][0] - mx0);
            float p01 = __expf(sacc[nt][1] - mx0);
            float p10 = __expf(sacc[nt][2] - mx1);
            float p11 = __expf(sacc[nt][3] - mx1);
            sum0 += p00 + p01;
            sum1 += p10 + p11;
            *(float2*)&Ps[r0][cc] = make_float2(
                __uint_as_float(f2tf32(p00)), __uint_as_float(f2tf32(p01)));
            *(float2*)&Ps[r0 + 8][cc] = make_float2(
                __uint_as_float(f2tf32(p10)), __uint_as_float(f2tf32(p11)));
        }
        #pragma unroll
        for (int o = 1; o <= 2; o <<= 1) {
            sum0 += __shfl_xor_sync(0xffffffffu, sum0, o);
            sum1 += __shfl_xor_sync(0xffffffffu, sum1, o);
        }
        l0 = l0 * rs0 + sum0;
        l1 = l1 * rs1 + sum1;
        #pragma unroll
        for (int nt = 0; nt < 8; nt++) {
            oacc[nt][0] *= rs0; oacc[nt][1] *= rs0;
            oacc[nt][2] *= rs1; oacc[nt][3] *= rs1;
        }
        __syncwarp();

        #pragma unroll
        for (int ks = 0; ks < 8; ks++) {
            const int kc = ks * 8;
            unsigned af[4];
            af[0] = __float_as_uint(Ps[r0][kc + c]);
            af[1] = __float_as_uint(Ps[r0 + 8][kc + c]);
            af[2] = __float_as_uint(Ps[r0][kc + c + 4]);
            af[3] = __float_as_uint(Ps[r0 + 8][kc + c + 4]);
            #pragma unroll
            for (int nt = 0; nt < 8; nt++) {
                unsigned bf[2];
                bf[0] = __float_as_uint(Vs[kc + c][nt * 8 + g]);
                bf[1] = __float_as_uint(Vs[kc + c + 4][nt * 8 + g]);
                mma_tf32(oacc[nt], af, bf);
            }
        }
    }

    const float inv0 = 1.0f / l0, inv1 = 1.0f / l1;
    const size_t row0 = (size_t)(b * TSEQ + qbase + r0) * EMB + h * 64;
    const size_t row1 = row0 + (size_t)8 * EMB;
    #pragma unroll
    for (int nt = 0; nt < 8; nt++) {
        const int cc = nt * 8 + 2 * c;
        *(float2*)&out[row0 + cc] = make_float2(
            __uint_as_float(f2tf32(oacc[nt][0] * inv0)),
            __uint_as_float(f2tf32(oacc[nt][1] * inv0)));
        *(float2*)&out[row1 + cc] = make_float2(
            __uint_as_float(f2tf32(oacc[nt][2] * inv1)),
            __uint_as_float(f2tf32(oacc[nt][3] * inv1)));
    }
}

// ---------------------------------------------------------------------------
static float* sym_addr(const void* symbol)
{
    void* p = nullptr;
    cudaGetSymbolAddress(&p, symbol);
    return (float*)p;
}

extern "C" void kernel_launch(void* const* d_in, const int* in_sizes, int n_in,
                              void* d_out, int out_size)
{
    (void)in_sizes; (void)n_in; (void)out_size;
    const float* x      = (const float*)d_in[0];
    const float* Wq     = (const float*)d_in[1];
    const float* bq     = (const float*)d_in[2];
    const float* Wk     = (const float*)d_in[3];
    const float* bk     = (const float*)d_in[4];
    const float* Wv     = (const float*)d_in[5];
    const float* bv     = (const float*)d_in[6];
    const float* Wo     = (const float*)d_in[7];
    const float* bo     = (const float*)d_in[8];
    const float* W1     = (const float*)d_in[9];
    const float* b1     = (const float*)d_in[10];
    const float* W2     = (const float*)d_in[11];
    const float* b2     = (const float*)d_in[12];
    const float* gamma1 = (const float*)d_in[13];
    const float* beta1  = (const float*)d_in[14];
    const float* gamma2 = (const float*)d_in[15];
    const float* beta2  = (const float*)d_in[16];
    float* out = (float*)d_out;

    float* xn   = sym_addr(g_xn);
    float* qb   = sym_addr(g_q);
    float* kb2  = sym_addr(g_k);
    float* vb2  = sym_addr(g_v);
    float* att  = sym_addr(g_att);
    float* x1   = sym_addr(g_x1);
    float* hb   = sym_addr(g_h);
    float* wt   = sym_addr(g_wt);
    float* bqkv = sym_addr(g_bqkv);
    float* wot  = sym_addr(g_wot);
    float* w1t  = sym_addr(g_w1t);
    float* w2t  = sym_addr(g_w2t);

    cudaFuncSetAttribute(tc_gemm<0>, cudaFuncAttributeMaxDynamicSharedMemorySize, SMEM_DYN);
    cudaFuncSetAttribute(tc_gemm<1>, cudaFuncAttributeMaxDynamicSharedMemorySize, SMEM_DYN);
    cudaFuncSetAttribute(tc_gemm<2>, cudaFuncAttributeMaxDynamicSharedMemorySize, SMEM_DYN);
    cudaFuncSetAttribute(attn_mma,  cudaFuncAttributeMaxDynamicSharedMemorySize, ATTN_SMEM);

    // Side stream for weight preprocessing, fork/join via events
    // (capture-safe: fork from the legacy stream, join before consumers).
    cudaStream_t s1;
    cudaStreamCreateWithFlags(&s1, cudaStreamNonBlocking);
    cudaEvent_t eFork, eQkvW, eMainW;
    cudaEventCreateWithFlags(&eFork,  cudaEventDisableTiming);
    cudaEventCreateWithFlags(&eQkvW,  cudaEventDisableTiming);
    cudaEventCreateWithFlags(&eMainW, cudaEventDisableTiming);

    cudaEventRecord(eFork, 0);
    cudaStreamWaitEvent(s1, eFork, 0);

    // side stream: QKV weight prep, then the other three weights
    trans_qkv<<<dim3(2, 32, 48), dim3(32, 8), 0, s1>>>(Wq, Wk, Wv, wt);
    pack_bias<<<12, 256, 0, s1>>>(bq, bk, bv, bqkv);
    cudaEventRecord(eQkvW, s1);
    trans_w<<<dim3(32, 32),  dim3(32, 8), 0, s1>>>(Wo, wot, EMB, EMB);
    trans_w<<<dim3(128, 32), dim3(32, 8), 0, s1>>>(W1, w1t, EMB, DFF);
    trans_w<<<dim3(32, 128), dim3(32, 8), 0, s1>>>(W2, w2t, DFF, EMB);
    cudaEventRecord(eMainW, s1);

    // main stream
    // 1. LN1 (overlaps trans_qkv)
    ln_kernel<<<MROWS / 8, 256>>>(x, gamma1, beta1, xn);
    // 2. fused QKV projection (needs wt/bqkv)
    cudaStreamWaitEvent(0, eQkvW, 0);
    tc_gemm<2><<<dim3(24, 32), 256, SMEM_DYN>>>(
        xn, wt, bqkv, nullptr, qb, kb2, vb2, 3 * EMB, EMB);
    // 3. causal attention (overlaps trans_w x3)
    attn_mma<<<dim3(TSEQ / 128, BATCH * HEADS), 256, ATTN_SMEM>>>(qb, kb2, vb2, att);
    // 4. output projection + residual (needs wot)
    cudaStreamWaitEvent(0, eMainW, 0);
    tc_gemm<1><<<dim3(8, 32), 256, SMEM_DYN>>>(
        att, wot, bo, x, x1, nullptr, nullptr, EMB, EMB);
    // 5. LN2
    ln_kernel<<<MROWS / 8, 256>>>(x1, gamma2, beta2, xn);
    // 6. FFN1 (relu)
    tc_gemm<0><<<dim3(32, 32), 256, SMEM_DYN>>>(
        xn, w1t, b1, nullptr, hb, nullptr, nullptr, DFF, EMB);
    // 7. FFN2 + residual -> out
    tc_gemm<1><<<dim3(8, 32), 256, SMEM_DYN>>>(
        hb, w2t, b2, x1, out, nullptr, nullptr, EMB, DFF);
}